// round 4
// baseline (speedup 1.0000x reference)
#include <cuda_runtime.h>
#include <cuda_bf16.h>
#include <cstdint>

// MX (block-32, E8M0 scale, E4M3 elements) quantize-dequantize.
// 4 float4 per thread (front-batched loads for MLP); within each chunk a warp
// covers 128 contiguous floats = 4 MX blocks; each block = 8 adjacent lanes.

#define VPT 4  // float4 chunks per thread

__device__ __forceinline__ float exp2i(int k) {
    // exact 2^k for k in [-126, 127]
    return __uint_as_float((unsigned)(k + 127) << 23);
}

__device__ __forceinline__ float qdq_e4m3(float x, float inv_scale, float scale) {
    float v = x * inv_scale;                 // exact: inv_scale is a power of two
    float mag = fminf(fabsf(v), 448.0f);     // saturate to E4M3 max
    float safe = fmaxf(mag, 0.015625f);      // 2^-6: subnormal region shares emin quantum
    int e = (int)((__float_as_uint(safe) >> 23) & 0xFF) - 127;   // exact floor(log2(safe))
    // quantum = 2^(e-3); RNE via rintf
    float q = rintf(mag * exp2i(3 - e)) * exp2i(e - 3);
    return copysignf(q, v) * scale;
}

__global__ void __launch_bounds__(256) mx_qdq_kernel(const float4* __restrict__ in,
                                                     float4* __restrict__ out,
                                                     int n4) {
    int base = blockIdx.x * (blockDim.x * VPT) + threadIdx.x;

    // ---- front-batched loads (MLP = VPT) ----
    float4 v[VPT];
    bool ok[VPT];
#pragma unroll
    for (int j = 0; j < VPT; j++) {
        int idx = base + j * blockDim.x;
        ok[j] = idx < n4;
        if (ok[j]) v[j] = in[idx];
    }

    // ---- per-chunk amax + 8-lane reduce (4 independent shuffle chains) ----
    float amax[VPT];
#pragma unroll
    for (int j = 0; j < VPT; j++) {
        float a = fmaxf(fmaxf(fabsf(v[j].x), fabsf(v[j].y)),
                        fmaxf(fabsf(v[j].z), fabsf(v[j].w)));
        if (!ok[j]) a = 0.0f;
        amax[j] = a;
    }
#pragma unroll
    for (int j = 0; j < VPT; j++) amax[j] = fmaxf(amax[j], __shfl_xor_sync(0xFFFFFFFFu, amax[j], 1));
#pragma unroll
    for (int j = 0; j < VPT; j++) amax[j] = fmaxf(amax[j], __shfl_xor_sync(0xFFFFFFFFu, amax[j], 2));
#pragma unroll
    for (int j = 0; j < VPT; j++) amax[j] = fmaxf(amax[j], __shfl_xor_sync(0xFFFFFFFFu, amax[j], 4));

    // ---- quantize-dequantize + store ----
#pragma unroll
    for (int j = 0; j < VPT; j++) {
        int idx = base + j * blockDim.x;
        if (!ok[j]) continue;

        float a = amax[j];
        float scale, inv_scale;
        if (a > 0.0f) {
            int ea = (int)((__float_as_uint(a) >> 23) & 0xFF) - 127; // floor(log2(amax))
            int se = ea - 8;                                          // ELEM_EMAX = 8
            se = max(-127, min(127, se));                             // E8M0 clip
            if (se > -127) {
                scale     = exp2i(se);
                inv_scale = exp2i(-se);
            } else {
                scale     = __uint_as_float(0x00400000u);             // 2^-127 (subnormal)
                inv_scale = exp2i(127);
            }
        } else {
            scale = 1.0f;
            inv_scale = 1.0f;
        }

        float4 o;
        o.x = qdq_e4m3(v[j].x, inv_scale, scale);
        o.y = qdq_e4m3(v[j].y, inv_scale, scale);
        o.z = qdq_e4m3(v[j].z, inv_scale, scale);
        o.w = qdq_e4m3(v[j].w, inv_scale, scale);
        out[idx] = o;
    }
}

extern "C" void kernel_launch(void* const* d_in, const int* in_sizes, int n_in,
                              void* d_out, int out_size) {
    const float* x = (const float*)d_in[0];
    float* out = (float*)d_out;
    int n = in_sizes[0];            // 4096*8192
    int n4 = n / 4;
    int threads = 256;
    int per_block = threads * VPT;
    int blocks = (n4 + per_block - 1) / per_block;
    mx_qdq_kernel<<<blocks, threads>>>((const float4*)x, (float4*)out, n4);
}

// round 6
// speedup vs baseline: 1.0284x; 1.0284x over previous
#include <cuda_runtime.h>
#include <cstdint>

// MX (block-32, E8M0 scale, E4M3 elements) quantize-dequantize.
// VPT float4 chunks per thread (front-batched loads for MLP). Within each
// chunk a warp covers 128 contiguous floats = 4 MX blocks; block = 8 lanes.
// Amax via integer abs-bit max + one redux.sync.max.u32 over the 8-lane group.

#define VPT 4

__device__ __forceinline__ float exp2i(int k) {
    // exact 2^k for k in [-126, 127]
    return __uint_as_float((unsigned)(k + 127) << 23);
}

__device__ __forceinline__ unsigned redux_max_u32(unsigned v, unsigned mask) {
    unsigned r;
    asm volatile("redux.sync.max.u32 %0, %1, %2;" : "=r"(r) : "r"(v), "r"(mask));
    return r;
}

__device__ __forceinline__ float qdq_e4m3(float x, float inv_scale, float scale) {
    float v = x * inv_scale;                 // exact: inv_scale is a power of two
    float mag = fminf(fabsf(v), 448.0f);     // saturate to E4M3 max
    float safe = fmaxf(mag, 0.015625f);      // 2^-6: subnormal region shares emin quantum
    int e = (int)((__float_as_uint(safe) >> 23) & 0xFF) - 127;   // exact floor(log2(safe))
    // quantum = 2^(e-3); RNE via rintf
    float q = rintf(mag * exp2i(3 - e)) * exp2i(e - 3);
    return copysignf(q, v) * scale;
}

__device__ __forceinline__ void scale_from_bits(unsigned am, float& scale, float& inv_scale) {
    if (am != 0u) {
        // se = floor(log2(amax)) - 8, clipped to [-127,127].
        // Exponent-field read is exact for normals; subnormal amax gives
        // field 0 -> se <= -135 -> clips to -127, matching the reference.
        int se = (int)(am >> 23) - 135;      // (biased_exp - 127) - 8
        if (se > -127) {
            scale     = exp2i(se);           // se <= 119 always, no upper clip needed
            inv_scale = exp2i(-se);
        } else {
            scale     = __uint_as_float(0x00400000u);  // 2^-127 (subnormal)
            inv_scale = exp2i(127);
        }
    } else {
        scale = 1.0f;
        inv_scale = 1.0f;
    }
}

template <bool EXACT>
__global__ void __launch_bounds__(256) mx_qdq_kernel(const float4* __restrict__ in,
                                                     float4* __restrict__ out,
                                                     int n4) {
    int base = blockIdx.x * (256 * VPT) + threadIdx.x;
    unsigned lane = threadIdx.x & 31u;
    unsigned gmask = 0xFFu << (lane & 24u);  // this thread's 8-lane MX-block group

    // ---- front-batched streaming loads (MLP = VPT) ----
    float4 v[VPT];
#pragma unroll
    for (int j = 0; j < VPT; j++) {
        int idx = base + j * 256;
        if (EXACT || idx < n4) v[j] = __ldcs(&in[idx]);
    }

    // ---- per-chunk abs-bit max, then one redux over the 8-lane group ----
    unsigned am[VPT];
#pragma unroll
    for (int j = 0; j < VPT; j++) {
        unsigned a = max(max(__float_as_uint(v[j].x) & 0x7FFFFFFFu,
                             __float_as_uint(v[j].y) & 0x7FFFFFFFu),
                         max(__float_as_uint(v[j].z) & 0x7FFFFFFFu,
                             __float_as_uint(v[j].w) & 0x7FFFFFFFu));
        if (!EXACT && (base + j * 256) >= n4) a = 0u;
        am[j] = a;
    }
#pragma unroll
    for (int j = 0; j < VPT; j++) am[j] = redux_max_u32(am[j], gmask);

    // ---- quantize-dequantize + streaming store ----
#pragma unroll
    for (int j = 0; j < VPT; j++) {
        int idx = base + j * 256;
        if (!EXACT && idx >= n4) continue;

        float scale, inv_scale;
        scale_from_bits(am[j], scale, inv_scale);

        float4 o;
        o.x = qdq_e4m3(v[j].x, inv_scale, scale);
        o.y = qdq_e4m3(v[j].y, inv_scale, scale);
        o.z = qdq_e4m3(v[j].z, inv_scale, scale);
        o.w = qdq_e4m3(v[j].w, inv_scale, scale);
        __stcs(&out[idx], o);
    }
}

extern "C" void kernel_launch(void* const* d_in, const int* in_sizes, int n_in,
                              void* d_out, int out_size) {
    const float4* x = (const float4*)d_in[0];
    float4* out = (float4*)d_out;
    int n = in_sizes[0];            // 4096*8192
    int n4 = n / 4;
    const int per_block = 256 * VPT;
    if (n4 % per_block == 0) {
        mx_qdq_kernel<true><<<n4 / per_block, 256>>>(x, out, n4);
    } else {
        mx_qdq_kernel<false><<<(n4 + per_block - 1) / per_block, 256>>>(x, out, n4);
    }
}

// round 9
// speedup vs baseline: 1.0630x; 1.0337x over previous
#include <cuda_runtime.h>
#include <cstdint>

// MX (block-32, E8M0 scale, E4M3 elements) quantize-dequantize.
// VPT=8 float4 chunks per thread (front-batched for MLP). Within each chunk a
// warp covers 128 contiguous floats = 4 MX blocks; each block = 8 lanes.
// Only the amax EXPONENT BYTE matters for the scale, so the 8 per-chunk
// exponents are packed into 2 u32s and reduced over the 8-lane group with a
// single shuffle tree using byte-wise max (6 SHFL + 6 VMAX4 for 8 blocks).

#define VPT 8

__device__ __forceinline__ float exp2i(int k) {
    // exact 2^k for k in [-126, 127]
    return __uint_as_float((unsigned)(k + 127) << 23);
}

__device__ __forceinline__ float qdq_e4m3(float x, float inv_scale, float scale) {
    float v = x * inv_scale;                 // exact: inv_scale is a power of two
    float mag = fminf(fabsf(v), 448.0f);     // saturate to E4M3 max
    float safe = fmaxf(mag, 0.015625f);      // 2^-6: subnormal region shares emin quantum
    int e = (int)((__float_as_uint(safe) >> 23) & 0xFF) - 127;   // exact floor(log2(safe))
    // quantum = 2^(e-3); RNE via rintf
    float q = rintf(mag * exp2i(3 - e)) * exp2i(e - 3);
    return copysignf(q, v) * scale;
}

template <bool EXACT>
__global__ void __launch_bounds__(256) mx_qdq_kernel(const float4* __restrict__ in,
                                                     float4* __restrict__ out,
                                                     int n4) {
    int base = blockIdx.x * (256 * VPT) + threadIdx.x;

    // ---- front-batched streaming loads (MLP = 8) ----
    float4 v[VPT];
#pragma unroll
    for (int j = 0; j < VPT; j++) {
        int idx = base + j * 256;
        if (EXACT || idx < n4) v[j] = __ldcs(&in[idx]);
    }

    // ---- per-chunk abs-bit max -> exponent byte, packed 4-per-u32 ----
    unsigned p0 = 0u, p1 = 0u;
#pragma unroll
    for (int j = 0; j < VPT; j++) {
        unsigned a = max(max(__float_as_uint(v[j].x) & 0x7FFFFFFFu,
                             __float_as_uint(v[j].y) & 0x7FFFFFFFu),
                         max(__float_as_uint(v[j].z) & 0x7FFFFFFFu,
                             __float_as_uint(v[j].w) & 0x7FFFFFFFu));
        if (!EXACT && (base + j * 256) >= n4) a = 0u;
        unsigned e = a >> 23;                // 8-bit exponent field (sign already masked)
        if (j < 4) p0 |= e << (8 * j);
        else       p1 |= e << (8 * (j - 4));
    }

    // ---- 8-lane group reduction, byte-wise max (blocks = 8 adjacent lanes) ----
#pragma unroll
    for (int m = 1; m <= 4; m <<= 1) {
        p0 = __vmaxu4(p0, __shfl_xor_sync(0xFFFFFFFFu, p0, m));
        p1 = __vmaxu4(p1, __shfl_xor_sync(0xFFFFFFFFu, p1, m));
    }

    // ---- quantize-dequantize + streaming store ----
#pragma unroll
    for (int j = 0; j < VPT; j++) {
        int idx = base + j * 256;
        if (!EXACT && idx >= n4) continue;

        unsigned e = ((j < 4) ? (p0 >> (8 * j)) : (p1 >> (8 * (j - 4)))) & 0xFFu;
        // shared_exp = clip(floor(log2(amax)) - 8, -127, 127); exponent-field
        // read is exact for normals; subnormal/zero amax -> e small -> clamps
        // to -127 (all-zero block outputs zeros under any scale, so the
        // reference's scale=1 special case is output-equivalent).
        int se = (int)e - 135;
        se = max(se, -127);
        float scale = (se == -127) ? __uint_as_float(0x00400000u)  // 2^-127 (subnormal)
                                   : exp2i(se);
        float inv_scale = exp2i(-se);        // exact: -se in [-119, 127]

        float4 o;
        o.x = qdq_e4m3(v[j].x, inv_scale, scale);
        o.y = qdq_e4m3(v[j].y, inv_scale, scale);
        o.z = qdq_e4m3(v[j].z, inv_scale, scale);
        o.w = qdq_e4m3(v[j].w, inv_scale, scale);
        __stcs(&out[idx], o);
    }
}

extern "C" void kernel_launch(void* const* d_in, const int* in_sizes, int n_in,
                              void* d_out, int out_size) {
    const float4* x = (const float4*)d_in[0];
    float4* out = (float4*)d_out;
    int n = in_sizes[0];            // 4096*8192
    int n4 = n / 4;
    const int per_block = 256 * VPT;
    if (n4 % per_block == 0) {
        mx_qdq_kernel<true><<<n4 / per_block, 256>>>(x, out, n4);
    } else {
        mx_qdq_kernel<false><<<(n4 + per_block - 1) / per_block, 256>>>(x, out, n4);
    }
}

// round 10
// speedup vs baseline: 1.0670x; 1.0037x over previous
#include <cuda_runtime.h>
#include <cstdint>

// MX (block-32, E8M0 scale, E4M3 elements) quantize-dequantize, fully in the
// BIT DOMAIN. Since the MX scale is a power of two, quant+dequant reduces to:
//   1) clamp |x| to 448*2^se            (integer min against precomputed bits)
//   2) normal range:  RNE-round the fp32 mantissa to 3 bits (integer add trick)
//      subnormal rng: round to fixed quantum 2^(se-9) via (y + C) - C magic add
// No scale multiplies, no rintf, no exp2 construction.
// VPT=4 float4 per thread; warp covers 128 contiguous floats = 4 MX blocks
// (8 lanes each). All 4 block-amax exponent bytes packed into ONE u32 and
// reduced with 3 x (shfl_xor + vmaxu4).

#define VPT 4

template <bool EXACT>
__global__ void __launch_bounds__(256) mx_qdq_kernel(const uint4* __restrict__ in,
                                                     uint4* __restrict__ out,
                                                     int n4) {
    int base = blockIdx.x * (256 * VPT) + threadIdx.x;

    // ---- front-batched streaming loads (MLP = 4) ----
    uint4 v[VPT];
#pragma unroll
    for (int j = 0; j < VPT; j++) {
        int idx = base + j * 256;
        if (EXACT || idx < n4) {
            const float4 f = __ldcs((const float4*)&in[idx]);
            v[j] = *(const uint4*)&f;
        }
    }

    // ---- per-chunk abs-bit max -> exponent byte, packed 4-per-u32 ----
    unsigned p = 0u;
#pragma unroll
    for (int j = 0; j < VPT; j++) {
        unsigned a = max(max(v[j].x & 0x7FFFFFFFu, v[j].y & 0x7FFFFFFFu),
                         max(v[j].z & 0x7FFFFFFFu, v[j].w & 0x7FFFFFFFu));
        if (!EXACT && (base + j * 256) >= n4) a = 0u;
        p |= (a >> 23) << (8 * j);
    }

    // ---- 8-lane group reduction, byte-wise max (block = 8 adjacent lanes) ----
#pragma unroll
    for (int m = 1; m <= 4; m <<= 1)
        p = __vmaxu4(p, __shfl_xor_sync(0xFFFFFFFFu, p, m));

    // ---- bit-domain quantize-dequantize + streaming store ----
#pragma unroll
    for (int j = 0; j < VPT; j++) {
        int idx = base + j * 256;
        if (!EXACT && idx >= n4) continue;

        unsigned E  = (p >> (8 * j)) & 0xFFu;   // exponent field of block amax
        unsigned mE = max(E, 8u);               // se = mE - 135 (E8M0 low clip at -127)
        // bits(448 * 2^se) = 1.75 * 2^(se+8), biased exponent = mE
        unsigned clampb = (mE << 23) | 0x600000u;
        // bits(2^(se-6)): normal when se-6 >= -126 (mE >= 14), else fp32-subnormal
        unsigned thresh = (mE >= 14u) ? ((mE - 14u) << 23) : (1u << (mE + 8u));
        // magic C = 1.5 * 2^(se+14): FADD RNE at ulp(C) = 2^(se-9) = subnormal quantum
        float C = __uint_as_float(((mE + 6u) << 23) | 0x400000u);

        uint4 u = v[j], o;
#pragma unroll
        for (int c = 0; c < 4; c++) {
            unsigned ub = (&u.x)[c];
            unsigned s  = ub & 0x80000000u;
            unsigned a  = min(ub & 0x7FFFFFFFu, clampb);       // saturate to 448*2^se
            // normal path: RNE to 3 mantissa bits (drop 20 bits)
            unsigned rn = (a + 0x7FFFFu + ((a >> 20) & 1u)) & 0xFFF00000u;
            // subnormal path: round to multiple of 2^(se-9)
            float fs = (__uint_as_float(a) + C) - C;
            unsigned r = (a >= thresh) ? rn : __float_as_uint(fs);
            (&o.x)[c] = r | s;
        }
        __stcs((float4*)&out[idx], *(const float4*)&o);
    }
}

extern "C" void kernel_launch(void* const* d_in, const int* in_sizes, int n_in,
                              void* d_out, int out_size) {
    const uint4* x = (const uint4*)d_in[0];
    uint4* out = (uint4*)d_out;
    int n = in_sizes[0];            // 4096*8192
    int n4 = n / 4;
    const int per_block = 256 * VPT;
    if (n4 % per_block == 0) {
        mx_qdq_kernel<true><<<n4 / per_block, 256>>>(x, out, n4);
    } else {
        mx_qdq_kernel<false><<<(n4 + per_block - 1) / per_block, 256>>>(x, out, n4);
    }
}